// round 12
// baseline (speedup 1.0000x reference)
#include <cuda_runtime.h>
#include <cuda_bf16.h>
#include <cuda_fp16.h>
#include <math.h>
#include <stdint.h>

#define B_ 4
#define L_ 1024
#define D_ 768
#define H_ 12
#define NE_ 42
#define M_ 4
#define P_ 512
#define BLK_ 64
#define NL_ 97
#define OFFSET_ 1
#define BP_ (B_*P_)          // 2048
#define KCH_ (D_/BLK_)       // 12 channel blocks
#define ISEG_ 3              // bilinear i-range split
#define KSLAB_ (ISEG_*KCH_)  // 36 partial slabs
#define NW_ 1536             // concat output width for extractors
#define WPITCH_ 136
#define WTILE_ (BLK_*WPITCH_)

typedef unsigned long long u64;
typedef unsigned int u32;

// ---------------- helpers ---------------------------------------------------
__device__ __forceinline__ u32 smem_u32(const void* p) {
    u32 a; asm("{ .reg .u64 t; cvta.to.shared.u64 t, %1; cvt.u32.u64 %0, t; }"
               : "=r"(a) : "l"(p));
    return a;
}
__device__ __forceinline__ u32 cvt_bf2(float lo, float hi) {
    u32 d; asm("cvt.rn.bf16x2.f32 %0, %1, %2;" : "=r"(d) : "f"(hi), "f"(lo));
    return d;
}
__device__ __forceinline__ float bf_lo_f(u32 c) { return __uint_as_float(c << 16); }
__device__ __forceinline__ float bf_hi_f(u32 c) { return __uint_as_float(c & 0xFFFF0000u); }

// fp16 pack/unpack (lo -> lower half)
__device__ __forceinline__ u32 cvt_h2(float lo, float hi) {
    u32 d; asm("cvt.rn.f16x2.f32 %0, %1, %2;" : "=r"(d) : "f"(hi), "f"(lo));
    return d;
}
__device__ __forceinline__ float2 h2_f2(u32 c) {
    __half2 h = *reinterpret_cast<__half2*>(&c);
    return __half22float2(h);
}

__device__ __forceinline__ void cpa16(u32 dst, const void* src) {
    asm volatile("cp.async.cg.shared.global [%0], [%1], 16;"
                 :: "r"(dst), "l"(src) : "memory");
}
__device__ __forceinline__ void cpa_commit() {
    asm volatile("cp.async.commit_group;" ::: "memory");
}
__device__ __forceinline__ void cpa_wait1() {
    asm volatile("cp.async.wait_group 1;" ::: "memory");
}
__device__ __forceinline__ void ldsm4(u32 addr, u32& r0, u32& r1, u32& r2, u32& r3) {
    asm volatile("ldmatrix.sync.aligned.m8n8.x4.shared.b16 {%0,%1,%2,%3}, [%4];"
                 : "=r"(r0), "=r"(r1), "=r"(r2), "=r"(r3) : "r"(addr));
}
__device__ __forceinline__ void ldsm4t(u32 addr, u32& r0, u32& r1, u32& r2, u32& r3) {
    asm volatile("ldmatrix.sync.aligned.m8n8.x4.trans.shared.b16 {%0,%1,%2,%3}, [%4];"
                 : "=r"(r0), "=r"(r1), "=r"(r2), "=r"(r3) : "r"(addr));
}
__device__ __forceinline__ void mma16816(float* d,
                                         u32 a0, u32 a1, u32 a2, u32 a3,
                                         u32 b0, u32 b1) {
    asm volatile(
        "mma.sync.aligned.m16n8k16.row.col.f32.bf16.bf16.f32 "
        "{%0,%1,%2,%3}, {%4,%5,%6,%7}, {%8,%9}, {%0,%1,%2,%3};"
        : "+f"(d[0]), "+f"(d[1]), "+f"(d[2]), "+f"(d[3])
        : "r"(a0), "r"(a1), "r"(a2), "r"(a3), "r"(b0), "r"(b1));
}
__device__ __forceinline__ void mma16816h(float* d,
                                          u32 a0, u32 a1, u32 a2, u32 a3,
                                          u32 b0, u32 b1) {
    asm volatile(
        "mma.sync.aligned.m16n8k16.row.col.f32.f16.f16.f32 "
        "{%0,%1,%2,%3}, {%4,%5,%6,%7}, {%8,%9}, {%0,%1,%2,%3};"
        : "+f"(d[0]), "+f"(d[1]), "+f"(d[2]), "+f"(d[3])
        : "r"(a0), "r"(a1), "r"(a2), "r"(a3), "r"(b0), "r"(b1));
}

// ---------------- scratch (device globals; no runtime allocation) ----------
__device__ float g_ent_att[B_*NE_*H_*L_];
__device__ __nv_bfloat16 g_entA_hi[256*D_], g_entA_lo[256*D_];  // 168 used
__device__ __nv_bfloat16 g_seq_hi[B_*L_*D_],  g_seq_lo[B_*L_*D_];
__device__ __nv_bfloat16 g_ht_hi[B_*P_*L_],   g_ht_lo[B_*P_*L_];
__device__ float g_rsp[2*BP_*D_];                // rs K-split fp32 partials
__device__ __nv_bfloat16 g_rs_hi[BP_*D_], g_rs_lo[BP_*D_];
__device__ __nv_bfloat16 g_W1c_hi[D_*NW_], g_W1c_lo[D_*NW_];
__device__ __nv_bfloat16 g_W2c_hi[D_*NW_], g_W2c_lo[D_*NW_];
__device__ float g_E0[256*NW_];
__device__ float g_ep[2*BP_*NW_];
__device__ float g_zs[BP_*D_], g_zo[BP_*D_];
__device__ float g_part[KSLAB_*BP_*NL_];
__device__ __half g_Wb[KCH_*BLK_*WTILE_];        // bilinear W, single fp16

// ---------------- fused prep kernel: split + padW + ent_emb + ent_att ------
#define SPLIT_SEQ (B_*L_*D_/2)
#define SPLIT_W   (D_*D_)
#define NB_SPLIT ((SPLIT_SEQ + 2*SPLIT_W + 255)/256)   // 10752
#define NB_PADW  (KCH_*BLK_)                            // 768
#define NB_EMB   (B_*NE_)                               // 168
#define NB_ATT   (B_*NE_*H_)                            // 2016
#define NB_PREP  (NB_SPLIT + NB_PADW + NB_EMB + NB_ATT)

__global__ void k_prep(const float* __restrict__ seq,
                       const float* __restrict__ Wh,
                       const float* __restrict__ Wt,
                       const float* __restrict__ Wbi,
                       const float* __restrict__ att,
                       const int* __restrict__ mpos) {
    int bb = blockIdx.x;
    int tid = threadIdx.x;
    if (bb < NB_SPLIT) {
        int i = bb*256 + tid;
        if (i < SPLIT_SEQ) {
            float v0 = seq[2*i], v1 = seq[2*i+1];
            u32 h = cvt_bf2(v0, v1);
            ((u32*)g_seq_hi)[i] = h;
            ((u32*)g_seq_lo)[i] = cvt_bf2(v0 - bf_lo_f(h), v1 - bf_hi_f(h));
            return;
        }
        int j = i - SPLIT_SEQ;
        if (j >= 2*SPLIT_W) return;
        int sel = (j >= SPLIT_W) ? 1 : 0;
        int off = j - sel*SPLIT_W;
        const float* W = sel ? Wt : Wh;
        int kg = (2*off) / D_;
        int d  = (2*off) % D_;
        float v0 = W[2*off], v1 = W[2*off+1];
        u32 h = cvt_bf2(v0, v1);
        u32 r = cvt_bf2(v0 - bf_lo_f(h), v1 - bf_hi_f(h));
        u32 *hi, *lo;
        int rowk;
        if (kg < D_) { hi = (u32*)g_W1c_hi; lo = (u32*)g_W1c_lo; rowk = kg; }
        else         { hi = (u32*)g_W2c_hi; lo = (u32*)g_W2c_lo; rowk = kg - D_; }
        int idx = rowk*(NW_/2) + sel*(D_/2) + d/2;
        hi[idx] = h;
        lo[idx] = r;
        return;
    }
    bb -= NB_SPLIT;
    if (bb < NB_PADW) {
        int ki = bb;
        u32* d0 = (u32*)(g_Wb + (size_t)ki*WTILE_);
        const float* src = Wbi + (size_t)ki*BLK_*NL_;
        for (int c = tid; c < WTILE_/8; c += 256) {
            int j = c / 17, c8 = (c % 17)*8;
            u32 h[4];
            #pragma unroll
            for (int e = 0; e < 4; e++) {
                int n0 = c8 + 2*e, n1 = n0 + 1;
                float v0 = (n0 < NL_) ? src[j*NL_ + n0] : 0.f;
                float v1 = (n1 < NL_) ? src[j*NL_ + n1] : 0.f;
                h[e] = cvt_h2(v0, v1);
            }
            int base = (j*WPITCH_ + c8) >> 1;
            *(uint4*)(d0 + base) = make_uint4(h[0], h[1], h[2], h[3]);
        }
        return;
    }
    bb -= NB_PADW;
    if (bb < NB_EMB) {
        int be = bb;
        int b  = be / NE_;
        int base = be * M_;
        int p0 = mpos[base+0] + OFFSET_;
        int p1 = mpos[base+1] + OFFSET_;
        int p2 = mpos[base+2] + OFFSET_;
        int p3 = mpos[base+3] + OFFSET_;
        const float* s0 = seq + ((size_t)b*L_ + p0)*D_;
        const float* s1 = seq + ((size_t)b*L_ + p1)*D_;
        const float* s2 = seq + ((size_t)b*L_ + p2)*D_;
        const float* s3 = seq + ((size_t)b*L_ + p3)*D_;
        for (int d = tid; d < D_; d += 256) {
            float x0 = s0[d], x1 = s1[d], x2 = s2[d], x3 = s3[d];
            float mx = fmaxf(fmaxf(x0,x1), fmaxf(x2,x3));
            float v = mx + logf(expf(x0-mx) + expf(x1-mx) + expf(x2-mx) + expf(x3-mx));
            __nv_bfloat16 hb = __float2bfloat16(v);
            g_entA_hi[(size_t)be*D_ + d] = hb;
            g_entA_lo[(size_t)be*D_ + d] = __float2bfloat16(v - __bfloat162float(hb));
        }
        return;
    }
    bb -= NB_EMB;
    if (bb < NB_ATT) {
        int h  = bb % H_;
        int be = bb / H_;
        int b  = be / NE_;
        int base = be * M_;
        const float* a = att + (((size_t)b*H_ + h)*L_)*L_;
        const float* r0 = a + (size_t)(mpos[base+0]+OFFSET_)*L_;
        const float* r1 = a + (size_t)(mpos[base+1]+OFFSET_)*L_;
        const float* r2 = a + (size_t)(mpos[base+2]+OFFSET_)*L_;
        const float* r3 = a + (size_t)(mpos[base+3]+OFFSET_)*L_;
        float* out = g_ent_att + ((size_t)be*H_ + h)*L_;
        for (int l = tid; l < L_; l += 256)
            out[l] = 0.25f * (r0[l] + r1[l] + r2[l] + r3[l]);
    }
}

// ---------------- kernel C: per-pair channel attention -> bf16 split -------
__global__ void k_ht(const int* __restrict__ hts) {
    int bp = blockIdx.x;
    int b  = bp / P_;
    int hi = hts[bp*2 + 0];
    int ti = hts[bp*2 + 1];
    const float* ah = g_ent_att + (size_t)(b*NE_ + hi)*H_*L_;
    const float* at = g_ent_att + (size_t)(b*NE_ + ti)*H_*L_;
    const int T = 256;
    float v[4];
    float lsum = 0.f;
    #pragma unroll
    for (int it = 0; it < 4; it++) {
        int l = threadIdx.x + it*T;
        float acc = 0.f;
        #pragma unroll
        for (int h = 0; h < H_; h++)
            acc += ah[h*L_ + l] * at[h*L_ + l];
        acc *= (1.f/H_);
        v[it] = acc;
        lsum += acc;
    }
    __shared__ float red[32];
    #pragma unroll
    for (int o = 16; o; o >>= 1) lsum += __shfl_down_sync(~0u, lsum, o);
    if ((threadIdx.x & 31) == 0) red[threadIdx.x >> 5] = lsum;
    __syncthreads();
    if (threadIdx.x < 8) {
        float t = red[threadIdx.x];
        #pragma unroll
        for (int o = 4; o; o >>= 1) t += __shfl_down_sync(0xffu, t, o);
        if (threadIdx.x == 0) red[0] = 1.f / (t + 1e-5f);
    }
    __syncthreads();
    float inv = red[0];
    #pragma unroll
    for (int it = 0; it < 4; it++) {
        int l = threadIdx.x + it*T;
        float vv = v[it] * inv;
        __nv_bfloat16 hb = __float2bfloat16(vv);
        g_ht_hi[(size_t)bp*L_ + l] = hb;
        g_ht_lo[(size_t)bp*L_ + l] = __float2bfloat16(vv - __bfloat162float(hb));
    }
}

// ---------------- generic mma GEMM core (128x128 tile, K-chunk 32) ---------
#define GA_PITCH 80
#define GB_PITCH 272
#define GSA_ 10240
#define GSB_ 8704
#define GSTAGE_ 37888
#define GSM_ 75776

__device__ __forceinline__ void g_load_stage(u32 sbase,
    const __nv_bfloat16* __restrict__ Ah, const __nv_bfloat16* __restrict__ Al,
    int lda,
    const __nv_bfloat16* __restrict__ Bh, const __nv_bfloat16* __restrict__ Bl,
    int ldb,
    int r0, int n0, int kc, int tid)
{
    #pragma unroll
    for (int t = 0; t < 2; t++) {
        int idx = tid + t*256;
        int row = idx >> 2, c = idx & 3;
        size_t so = (size_t)(r0+row)*lda + kc + c*8;
        cpa16(sbase + row*GA_PITCH + c*16, Ah + so);
        cpa16(sbase + GSA_ + row*GA_PITCH + c*16, Al + so);
    }
    #pragma unroll
    for (int t = 0; t < 2; t++) {
        int idx = tid + t*256;
        int row = idx >> 4, c = idx & 15;
        size_t so = (size_t)(kc+row)*ldb + n0 + c*8;
        cpa16(sbase + 2*GSA_ + row*GB_PITCH + c*16, Bh + so);
        cpa16(sbase + 2*GSA_ + GSB_ + row*GB_PITCH + c*16, Bl + so);
    }
}

__device__ __forceinline__ void g_compute(u32 sbase, int w, int l,
                                          float (*acc)[4]) {
    int wm = w >> 1, wn = w & 1;
    u32 abase = sbase + (u32)((wm*32 + (l&15))*GA_PITCH + (l>>4)*16);
    u32 bbase = sbase + 2*GSA_ +
                (u32)((l&15)*GB_PITCH + (wn*64 + (l>>4)*8)*2);
    #pragma unroll
    for (int kk = 0; kk < 2; kk++) {
        u32 ah[2][4], al[2][4];
        #pragma unroll
        for (int mi = 0; mi < 2; mi++) {
            ldsm4(abase + mi*16*GA_PITCH + kk*32,
                  ah[mi][0], ah[mi][1], ah[mi][2], ah[mi][3]);
            ldsm4(abase + GSA_ + mi*16*GA_PITCH + kk*32,
                  al[mi][0], al[mi][1], al[mi][2], al[mi][3]);
        }
        u32 bb = bbase + kk*16*GB_PITCH;
        #pragma unroll
        for (int ntp = 0; ntp < 4; ntp++) {
            u32 b0,b1,b2,b3, c0,c1,c2,c3;
            ldsm4t(bb + ntp*32, b0,b1,b2,b3);
            ldsm4t(bb + GSB_ + ntp*32, c0,c1,c2,c3);
            #pragma unroll
            for (int mi = 0; mi < 2; mi++) {
                float* A0 = acc[mi*8 + 2*ntp];
                float* A1 = acc[mi*8 + 2*ntp + 1];
                mma16816(A0, ah[mi][0],ah[mi][1],ah[mi][2],ah[mi][3], b0,b1);
                mma16816(A1, ah[mi][0],ah[mi][1],ah[mi][2],ah[mi][3], b2,b3);
                mma16816(A0, ah[mi][0],ah[mi][1],ah[mi][2],ah[mi][3], c0,c1);
                mma16816(A1, ah[mi][0],ah[mi][1],ah[mi][2],ah[mi][3], c2,c3);
                mma16816(A0, al[mi][0],al[mi][1],al[mi][2],al[mi][3], b0,b1);
                mma16816(A1, al[mi][0],al[mi][1],al[mi][2],al[mi][3], b2,b3);
            }
        }
    }
}

// full GEMM body with fp32 epilogue at out[row*ldo + col]
__device__ __forceinline__ void gemm_body(u32 sb, int tid, int w, int l,
    const __nv_bfloat16* Ah, const __nv_bfloat16* Al, int lda,
    const __nv_bfloat16* Bh, const __nv_bfloat16* Bl, int ldb,
    int r0, int n0, int kb, int NK, float* out, int ldo)
{
    float acc[16][4];
    #pragma unroll
    for (int f = 0; f < 16; f++)
        #pragma unroll
        for (int e = 0; e < 4; e++) acc[f][e] = 0.f;
    g_load_stage(sb, Ah, Al, lda, Bh, Bl, ldb, r0, n0, kb, tid);  cpa_commit();
    g_load_stage(sb+GSTAGE_, Ah, Al, lda, Bh, Bl, ldb, r0, n0, kb+32, tid); cpa_commit();
    for (int i = 0; i < NK; i++) {
        cpa_wait1(); __syncthreads();
        g_compute(sb + (i&1)*GSTAGE_, w, l, acc);
        __syncthreads();
        if (i + 2 < NK)
            g_load_stage(sb + (i&1)*GSTAGE_, Ah, Al, lda, Bh, Bl, ldb, r0, n0, kb+(i+2)*32, tid);
        cpa_commit();
    }
    int wm = w >> 1, wn = w & 1, g = l >> 2, tg = l & 3;
    #pragma unroll
    for (int mi = 0; mi < 2; mi++) {
        int row = r0 + wm*32 + mi*16 + g;
        #pragma unroll
        for (int f = 0; f < 8; f++) {
            int col = n0 + wn*64 + f*8 + tg*2;
            float* a4 = acc[mi*8 + f];
            out[(size_t)row*ldo + col]       = a4[0];
            out[(size_t)row*ldo + col+1]     = a4[1];
            out[(size_t)(row+8)*ldo + col]   = a4[2];
            out[(size_t)(row+8)*ldo + col+1] = a4[3];
        }
    }
}

// ---------------- kernel D: rs GEMM, K-split x2, 2 blocks/SM ---------------
__global__ void __launch_bounds__(256, 2) k_rs_mma() {
    extern __shared__ char smem[];
    u32 sb = smem_u32(smem);
    int tid = threadIdx.x, w = tid >> 5, l = tid & 31;
    int r0 = blockIdx.x * 128, n0 = blockIdx.y * 128;
    int khalf = blockIdx.z;
    int b = r0 / P_;
    gemm_body(sb, tid, w, l,
              g_ht_hi, g_ht_lo, L_,
              g_seq_hi + (size_t)b*L_*D_, g_seq_lo + (size_t)b*L_*D_, D_,
              r0, n0, khalf*(L_/2), (L_/2)/32,
              g_rsp + (size_t)khalf*BP_*D_, D_);
}

// ---------------- kernel D2: combine rs partials -> bf16 split -------------
__global__ void k_rs_comb() {
    int i2 = blockIdx.x*256 + threadIdx.x;
    if (i2 >= BP_*D_/2) return;
    float2 a = ((const float2*)g_rsp)[i2];
    float2 b = ((const float2*)(g_rsp + (size_t)BP_*D_))[i2];
    float v0 = a.x + b.x, v1 = a.y + b.y;
    u32 hp = cvt_bf2(v0, v1);
    u32 lp = cvt_bf2(v0 - bf_lo_f(hp), v1 - bf_hi_f(hp));
    ((u32*)g_rs_hi)[i2] = hp;
    ((u32*)g_rs_lo)[i2] = lp;
}

// ---------------- kernel E: merged E1 (384 blocks) + E0 (24 blocks) --------
#define NBE1_ (16*12*2)      // 384
__global__ void __launch_bounds__(256, 2) k_E01() {
    extern __shared__ char smem[];
    u32 sb = smem_u32(smem);
    int tid = threadIdx.x, w = tid >> 5, l = tid & 31;
    int bb = blockIdx.x;
    if (bb < NBE1_) {
        int khalf = bb & 1;
        int t = bb >> 1;
        int r0 = (t & 15) * 128, n0 = (t >> 4) * 128;
        gemm_body(sb, tid, w, l,
                  g_rs_hi, g_rs_lo, D_,
                  g_W2c_hi, g_W2c_lo, NW_,
                  r0, n0, khalf*(D_/2), (D_/2)/32,
                  g_ep + (size_t)khalf*BP_*NW_, NW_);
    } else {
        int t = bb - NBE1_;                  // 0..23
        int r0 = (t & 1) * 128, n0 = (t >> 1) * 128;
        gemm_body(sb, tid, w, l,
                  g_entA_hi, g_entA_lo, D_,
                  g_W1c_hi, g_W1c_lo, NW_,
                  r0, n0, 0, D_/32,
                  g_E0, NW_);
    }
}

// ---------------- kernel T: combine E0(gather) + E1 partials + tanh --------
__global__ void k_tanh(const int* __restrict__ hts,
                       const float* __restrict__ bh, const float* __restrict__ bt) {
    int i4 = blockIdx.x*blockDim.x + threadIdx.x;
    if (i4 >= BP_*NW_/4) return;
    int row = (i4*4) / NW_;
    int n   = (i4*4) % NW_;
    int sel = (n >= D_) ? 1 : 0;
    int col = n - sel*D_;
    int b = row / P_;
    int eidx = hts[row*2 + sel];
    int entrow = b*NE_ + eidx;
    const float4 a = ((const float4*)(g_ep))[i4];
    const float4 c = ((const float4*)(g_ep + (size_t)BP_*NW_))[i4];
    const float4 e0 = *(const float4*)(g_E0 + (size_t)entrow*NW_ + n);
    const float* bias = sel ? bt : bh;
    float4 bb = *(const float4*)(bias + col);
    float* out = sel ? g_zo : g_zs;
    float4 o;
    o.x = tanhf(a.x + c.x + e0.x + bb.x);
    o.y = tanhf(a.y + c.y + e0.y + bb.y);
    o.z = tanhf(a.z + c.z + e0.z + bb.z);
    o.w = tanhf(a.w + c.w + e0.w + bb.w);
    *(float4*)(out + (size_t)row*D_ + col) = o;
}

// ---------------- kernel F: bilinear classifier, fp16 2-MMA ----------------
#define SM_ZSB 0                        // [128][24] f32 = 12288
#define SM_WB  12288
#define WSTAGE2_ 17408                  // one fp16 W tile per stage
#define SMEMB_ (SM_WB + 2*WSTAGE2_)     // 47104

__global__ void __launch_bounds__(256, 2) k_bilinear_mma() {
    extern __shared__ char smem[];
    float* zs_s = (float*)(smem + SM_ZSB);
    u32 sw = smem_u32(smem) + SM_WB;
    int tid = threadIdx.x, w = tid >> 5, l = tid & 31;
    int g = l >> 2, tg = l & 3;
    int k  = blockIdx.y;
    int r0 = blockIdx.x * 128;
    int iseg = blockIdx.z;
    int i0 = iseg*21, i1 = (iseg == ISEG_-1) ? BLK_ : (i0 + 21);
    int LEN = i1 - i0;

    // ---- prologue: W stages for i0, i0+1 ----
    #pragma unroll
    for (int p = 0; p < 2; p++) {
        int ii = i0 + p;
        const char* src = (const char*)(g_Wb + (size_t)(k*BLK_ + ii)*WTILE_);
        u32 dst = sw + (ii & 1)*WSTAGE2_;
        #pragma unroll
        for (int t = 0; t < 5; t++) {
            int idx = tid + t*256;
            if (idx < 1088) cpa16(dst + idx*16, src + idx*16);
        }
        cpa_commit();
    }

    int rg = w*16 + g;
    // ---- zo fragment values from global (one-time) ----
    float2 zoA[4][2], zoB[4][2];
    {
        const float* zor0 = g_zo + (size_t)(r0+rg)*D_ + k*BLK_;
        const float* zor1 = g_zo + (size_t)(r0+rg+8)*D_ + k*BLK_;
        #pragma unroll
        for (int jc = 0; jc < 4; jc++) {
            zoA[jc][0] = *(const float2*)(zor0 + jc*16 + tg*2);
            zoA[jc][1] = *(const float2*)(zor0 + jc*16 + tg*2 + 8);
            zoB[jc][0] = *(const float2*)(zor1 + jc*16 + tg*2);
            zoB[jc][1] = *(const float2*)(zor1 + jc*16 + tg*2 + 8);
        }
    }
    // ---- stage zs i-range slice [128][LEN] ----
    for (int idx = tid; idx < 128*LEN; idx += 256) {
        int r = idx / LEN, c = idx % LEN;
        zs_s[r*24 + c] = g_zs[(size_t)(r0+r)*D_ + k*BLK_ + i0 + c];
    }

    float acc[14][4];
    #pragma unroll
    for (int t = 0; t < 14; t++)
        #pragma unroll
        for (int e = 0; e < 4; e++) acc[t][e] = 0.f;

    u32 laneoff = (u32)((l & 15)*272 + (l >> 4)*16);

    for (int i = i0; i < i1; i++) {
        int s = i & 1;
        cpa_wait1();
        __syncthreads();
        float zs0 = zs_s[rg*24 + (i - i0)];
        float zs1 = zs_s[(rg+8)*24 + (i - i0)];
        u32 sbase = sw + s*WSTAGE2_;
        #pragma unroll
        for (int jc = 0; jc < 4; jc++) {
            float p0x = zs0*zoA[jc][0].x, p0y = zs0*zoA[jc][0].y;
            float p1x = zs1*zoB[jc][0].x, p1y = zs1*zoB[jc][0].y;
            float p2x = zs0*zoA[jc][1].x, p2y = zs0*zoA[jc][1].y;
            float p3x = zs1*zoB[jc][1].x, p3y = zs1*zoB[jc][1].y;
            u32 a0h = cvt_h2(p0x, p0y);
            u32 a1h = cvt_h2(p1x, p1y);
            u32 a2h = cvt_h2(p2x, p2y);
            u32 a3h = cvt_h2(p3x, p3y);
            float2 b0f = h2_f2(a0h), b1f = h2_f2(a1h);
            float2 b2f = h2_f2(a2h), b3f = h2_f2(a3h);
            u32 a0r = cvt_h2(p0x - b0f.x, p0y - b0f.y);
            u32 a1r = cvt_h2(p1x - b1f.x, p1y - b1f.y);
            u32 a2r = cvt_h2(p2x - b2f.x, p2y - b2f.y);
            u32 a3r = cvt_h2(p3x - b3f.x, p3y - b3f.y);
            u32 rowb = sbase + (u32)(jc*16*272) + laneoff;
            #pragma unroll
            for (int ntp = 0; ntp < 7; ntp++) {
                u32 b0, b1, b2, b3;
                ldsm4t(rowb + ntp*32, b0, b1, b2, b3);
                mma16816h(acc[2*ntp],   a0h,a1h,a2h,a3h, b0, b1);
                mma16816h(acc[2*ntp+1], a0h,a1h,a2h,a3h, b2, b3);
                mma16816h(acc[2*ntp],   a0r,a1r,a2r,a3r, b0, b1);
                mma16816h(acc[2*ntp+1], a0r,a1r,a2r,a3r, b2, b3);
            }
        }
        __syncthreads();
        if (i + 2 < i1) {
            const char* src = (const char*)(g_Wb + (size_t)(k*BLK_ + i + 2)*WTILE_);
            u32 dst = sw + s*WSTAGE2_;
            #pragma unroll
            for (int t = 0; t < 5; t++) {
                int idx = tid + t*256;
                if (idx < 1088) cpa16(dst + idx*16, src + idx*16);
            }
        }
        cpa_commit();
    }

    int slab = iseg*KCH_ + k;
    float* base0 = g_part + ((size_t)slab*BP_ + r0 + rg)*NL_;
    float* base1 = g_part + ((size_t)slab*BP_ + r0 + rg + 8)*NL_;
    #pragma unroll
    for (int nt = 0; nt < 13; nt++) {
        int n0 = nt*8 + tg*2;
        if (n0 < NL_) { base0[n0] = acc[nt][0]; base1[n0] = acc[nt][2]; }
        if (n0 + 1 < NL_) { base0[n0+1] = acc[nt][1]; base1[n0+1] = acc[nt][3]; }
    }
}

// ---------------- kernel G: reduce split-K partials + bias -----------------
__global__ void k_reduce(const float* __restrict__ bbi, float* __restrict__ out) {
    int idx = blockIdx.x*256 + threadIdx.x;
    if (idx >= BP_*NL_) return;
    int n = idx % NL_;
    float s = bbi[n];
    #pragma unroll
    for (int k = 0; k < KSLAB_; k++)
        s += g_part[(size_t)k*BP_*NL_ + idx];
    out[idx] = s;
}

// ---------------- launch ---------------------------------------------------
extern "C" void kernel_launch(void* const* d_in, const int* in_sizes, int n_in,
                              void* d_out, int out_size) {
    const float* seq  = (const float*)d_in[0];
    const float* att  = (const float*)d_in[1];
    const int*   mpos = (const int*)d_in[2];
    const int*   hts  = (const int*)d_in[3];
    const float* Wh   = (const float*)d_in[4];
    const float* bh   = (const float*)d_in[5];
    const float* Wt   = (const float*)d_in[6];
    const float* bt   = (const float*)d_in[7];
    const float* Wbi  = (const float*)d_in[8];
    const float* bbi  = (const float*)d_in[9];
    float* out = (float*)d_out;

    static bool attr_set = false;
    if (!attr_set) {
        cudaFuncSetAttribute(k_bilinear_mma,
            cudaFuncAttributeMaxDynamicSharedMemorySize, SMEMB_);
        cudaFuncSetAttribute(k_rs_mma,
            cudaFuncAttributeMaxDynamicSharedMemorySize, GSM_);
        cudaFuncSetAttribute(k_E01,
            cudaFuncAttributeMaxDynamicSharedMemorySize, GSM_);
        attr_set = true;
    }

    k_prep<<<NB_PREP, 256>>>(seq, Wh, Wt, Wbi, att, mpos);
    k_ht<<<B_*P_, 256>>>(hts);
    k_rs_mma<<<dim3(BP_/128, D_/128, 2), 256, GSM_>>>();
    k_rs_comb<<<(BP_*D_/2 + 255)/256, 256>>>();
    k_E01<<<NBE1_ + 24, 256, GSM_>>>();
    k_tanh<<<(BP_*NW_/4 + 255)/256, 256>>>(hts, bh, bt);
    k_bilinear_mma<<<dim3(BP_/128, KCH_, ISEG_), 256, SMEMB_>>>();
    k_reduce<<<(BP_*NL_ + 255)/256, 256>>>(bbi, out);
}

// round 13
// speedup vs baseline: 1.7242x; 1.7242x over previous
#include <cuda_runtime.h>
#include <cuda_bf16.h>
#include <cuda_fp16.h>
#include <math.h>
#include <stdint.h>

#define B_ 4
#define L_ 1024
#define D_ 768
#define H_ 12
#define NE_ 42
#define M_ 4
#define P_ 512
#define BLK_ 64
#define NL_ 97
#define OFFSET_ 1
#define BP_ (B_*P_)          // 2048
#define KCH_ (D_/BLK_)       // 12 channel blocks
#define ISEG_ 3              // bilinear i-range split
#define KSLAB_ (ISEG_*KCH_)  // 36 partial slabs
#define NW_ 1536             // concat output width for extractors
#define WPITCH_ 136
#define WTILE_ (BLK_*WPITCH_)

typedef unsigned long long u64;
typedef unsigned int u32;

// ---------------- helpers ---------------------------------------------------
__device__ __forceinline__ u32 smem_u32(const void* p) {
    u32 a; asm("{ .reg .u64 t; cvta.to.shared.u64 t, %1; cvt.u32.u64 %0, t; }"
               : "=r"(a) : "l"(p));
    return a;
}
__device__ __forceinline__ u32 cvt_bf2(float lo, float hi) {
    u32 d; asm("cvt.rn.bf16x2.f32 %0, %1, %2;" : "=r"(d) : "f"(hi), "f"(lo));
    return d;
}
__device__ __forceinline__ float bf_lo_f(u32 c) { return __uint_as_float(c << 16); }
__device__ __forceinline__ float bf_hi_f(u32 c) { return __uint_as_float(c & 0xFFFF0000u); }

// fp16 pack (lo -> lower half)
__device__ __forceinline__ u32 cvt_h2(float lo, float hi) {
    u32 d; asm("cvt.rn.f16x2.f32 %0, %1, %2;" : "=r"(d) : "f"(hi), "f"(lo));
    return d;
}

__device__ __forceinline__ void cpa16(u32 dst, const void* src) {
    asm volatile("cp.async.cg.shared.global [%0], [%1], 16;"
                 :: "r"(dst), "l"(src) : "memory");
}
__device__ __forceinline__ void cpa_commit() {
    asm volatile("cp.async.commit_group;" ::: "memory");
}
__device__ __forceinline__ void cpa_wait1() {
    asm volatile("cp.async.wait_group 1;" ::: "memory");
}
__device__ __forceinline__ void ldsm4(u32 addr, u32& r0, u32& r1, u32& r2, u32& r3) {
    asm volatile("ldmatrix.sync.aligned.m8n8.x4.shared.b16 {%0,%1,%2,%3}, [%4];"
                 : "=r"(r0), "=r"(r1), "=r"(r2), "=r"(r3) : "r"(addr));
}
__device__ __forceinline__ void ldsm4t(u32 addr, u32& r0, u32& r1, u32& r2, u32& r3) {
    asm volatile("ldmatrix.sync.aligned.m8n8.x4.trans.shared.b16 {%0,%1,%2,%3}, [%4];"
                 : "=r"(r0), "=r"(r1), "=r"(r2), "=r"(r3) : "r"(addr));
}
__device__ __forceinline__ void mma16816(float* d,
                                         u32 a0, u32 a1, u32 a2, u32 a3,
                                         u32 b0, u32 b1) {
    asm volatile(
        "mma.sync.aligned.m16n8k16.row.col.f32.bf16.bf16.f32 "
        "{%0,%1,%2,%3}, {%4,%5,%6,%7}, {%8,%9}, {%0,%1,%2,%3};"
        : "+f"(d[0]), "+f"(d[1]), "+f"(d[2]), "+f"(d[3])
        : "r"(a0), "r"(a1), "r"(a2), "r"(a3), "r"(b0), "r"(b1));
}
__device__ __forceinline__ void mma16816h(float* d,
                                          u32 a0, u32 a1, u32 a2, u32 a3,
                                          u32 b0, u32 b1) {
    asm volatile(
        "mma.sync.aligned.m16n8k16.row.col.f32.f16.f16.f32 "
        "{%0,%1,%2,%3}, {%4,%5,%6,%7}, {%8,%9}, {%0,%1,%2,%3};"
        : "+f"(d[0]), "+f"(d[1]), "+f"(d[2]), "+f"(d[3])
        : "r"(a0), "r"(a1), "r"(a2), "r"(a3), "r"(b0), "r"(b1));
}

// ---------------- scratch (device globals; no runtime allocation) ----------
__device__ float g_ent_att[B_*NE_*H_*L_];
__device__ __nv_bfloat16 g_entA_hi[256*D_], g_entA_lo[256*D_];  // 168 used
__device__ __nv_bfloat16 g_seq_hi[B_*L_*D_],  g_seq_lo[B_*L_*D_];
__device__ __nv_bfloat16 g_ht_hi[B_*P_*L_],   g_ht_lo[B_*P_*L_];
__device__ float g_rsp[2*BP_*D_];                // rs K-split fp32 partials
__device__ __nv_bfloat16 g_rs_hi[BP_*D_], g_rs_lo[BP_*D_];
__device__ __nv_bfloat16 g_W1c_hi[D_*NW_], g_W1c_lo[D_*NW_];
__device__ __nv_bfloat16 g_W2c_hi[D_*NW_], g_W2c_lo[D_*NW_];
__device__ float g_E0[256*NW_];
__device__ float g_ep[2*BP_*NW_];
__device__ float g_zs[BP_*D_], g_zo[BP_*D_];
__device__ float g_part[KSLAB_*BP_*NL_];
__device__ __half g_Wb[KCH_*BLK_*WTILE_];        // bilinear W, single fp16

// ---------------- fused prep kernel: split + padW + ent_emb + ent_att ------
#define SPLIT_SEQ (B_*L_*D_/2)
#define SPLIT_W   (D_*D_)
#define NB_SPLIT ((SPLIT_SEQ + 2*SPLIT_W + 255)/256)   // 10752
#define NB_PADW  (KCH_*BLK_)                            // 768
#define NB_EMB   (B_*NE_)                               // 168
#define NB_ATT   (B_*NE_*H_)                            // 2016
#define NB_PREP  (NB_SPLIT + NB_PADW + NB_EMB + NB_ATT)

__global__ void k_prep(const float* __restrict__ seq,
                       const float* __restrict__ Wh,
                       const float* __restrict__ Wt,
                       const float* __restrict__ Wbi,
                       const float* __restrict__ att,
                       const int* __restrict__ mpos) {
    int bb = blockIdx.x;
    int tid = threadIdx.x;
    if (bb < NB_SPLIT) {
        int i = bb*256 + tid;
        if (i < SPLIT_SEQ) {
            float v0 = seq[2*i], v1 = seq[2*i+1];
            u32 h = cvt_bf2(v0, v1);
            ((u32*)g_seq_hi)[i] = h;
            ((u32*)g_seq_lo)[i] = cvt_bf2(v0 - bf_lo_f(h), v1 - bf_hi_f(h));
            return;
        }
        int j = i - SPLIT_SEQ;
        if (j >= 2*SPLIT_W) return;
        int sel = (j >= SPLIT_W) ? 1 : 0;
        int off = j - sel*SPLIT_W;
        const float* W = sel ? Wt : Wh;
        int kg = (2*off) / D_;
        int d  = (2*off) % D_;
        float v0 = W[2*off], v1 = W[2*off+1];
        u32 h = cvt_bf2(v0, v1);
        u32 r = cvt_bf2(v0 - bf_lo_f(h), v1 - bf_hi_f(h));
        u32 *hi, *lo;
        int rowk;
        if (kg < D_) { hi = (u32*)g_W1c_hi; lo = (u32*)g_W1c_lo; rowk = kg; }
        else         { hi = (u32*)g_W2c_hi; lo = (u32*)g_W2c_lo; rowk = kg - D_; }
        int idx = rowk*(NW_/2) + sel*(D_/2) + d/2;
        hi[idx] = h;
        lo[idx] = r;
        return;
    }
    bb -= NB_SPLIT;
    if (bb < NB_PADW) {
        int ki = bb;
        u32* d0 = (u32*)(g_Wb + (size_t)ki*WTILE_);
        const float* src = Wbi + (size_t)ki*BLK_*NL_;
        for (int c = tid; c < WTILE_/8; c += 256) {
            int j = c / 17, c8 = (c % 17)*8;
            u32 h[4];
            #pragma unroll
            for (int e = 0; e < 4; e++) {
                int n0 = c8 + 2*e, n1 = n0 + 1;
                float v0 = (n0 < NL_) ? src[j*NL_ + n0] : 0.f;
                float v1 = (n1 < NL_) ? src[j*NL_ + n1] : 0.f;
                h[e] = cvt_h2(v0, v1);
            }
            int base = (j*WPITCH_ + c8) >> 1;
            *(uint4*)(d0 + base) = make_uint4(h[0], h[1], h[2], h[3]);
        }
        return;
    }
    bb -= NB_PADW;
    if (bb < NB_EMB) {
        int be = bb;
        int b  = be / NE_;
        int base = be * M_;
        int p0 = mpos[base+0] + OFFSET_;
        int p1 = mpos[base+1] + OFFSET_;
        int p2 = mpos[base+2] + OFFSET_;
        int p3 = mpos[base+3] + OFFSET_;
        const float* s0 = seq + ((size_t)b*L_ + p0)*D_;
        const float* s1 = seq + ((size_t)b*L_ + p1)*D_;
        const float* s2 = seq + ((size_t)b*L_ + p2)*D_;
        const float* s3 = seq + ((size_t)b*L_ + p3)*D_;
        for (int d = tid; d < D_; d += 256) {
            float x0 = s0[d], x1 = s1[d], x2 = s2[d], x3 = s3[d];
            float mx = fmaxf(fmaxf(x0,x1), fmaxf(x2,x3));
            float v = mx + logf(expf(x0-mx) + expf(x1-mx) + expf(x2-mx) + expf(x3-mx));
            __nv_bfloat16 hb = __float2bfloat16(v);
            g_entA_hi[(size_t)be*D_ + d] = hb;
            g_entA_lo[(size_t)be*D_ + d] = __float2bfloat16(v - __bfloat162float(hb));
        }
        return;
    }
    bb -= NB_EMB;
    if (bb < NB_ATT) {
        int h  = bb % H_;
        int be = bb / H_;
        int b  = be / NE_;
        int base = be * M_;
        const float* a = att + (((size_t)b*H_ + h)*L_)*L_;
        const float* r0 = a + (size_t)(mpos[base+0]+OFFSET_)*L_;
        const float* r1 = a + (size_t)(mpos[base+1]+OFFSET_)*L_;
        const float* r2 = a + (size_t)(mpos[base+2]+OFFSET_)*L_;
        const float* r3 = a + (size_t)(mpos[base+3]+OFFSET_)*L_;
        float* out = g_ent_att + ((size_t)be*H_ + h)*L_;
        for (int l = tid; l < L_; l += 256)
            out[l] = 0.25f * (r0[l] + r1[l] + r2[l] + r3[l]);
    }
}

// ---------------- kernel C: per-pair channel attention -> bf16 split -------
__global__ void k_ht(const int* __restrict__ hts) {
    int bp = blockIdx.x;
    int b  = bp / P_;
    int hi = hts[bp*2 + 0];
    int ti = hts[bp*2 + 1];
    const float* ah = g_ent_att + (size_t)(b*NE_ + hi)*H_*L_;
    const float* at = g_ent_att + (size_t)(b*NE_ + ti)*H_*L_;
    const int T = 256;
    float v[4];
    float lsum = 0.f;
    #pragma unroll
    for (int it = 0; it < 4; it++) {
        int l = threadIdx.x + it*T;
        float acc = 0.f;
        #pragma unroll
        for (int h = 0; h < H_; h++)
            acc += ah[h*L_ + l] * at[h*L_ + l];
        acc *= (1.f/H_);
        v[it] = acc;
        lsum += acc;
    }
    __shared__ float red[32];
    #pragma unroll
    for (int o = 16; o; o >>= 1) lsum += __shfl_down_sync(~0u, lsum, o);
    if ((threadIdx.x & 31) == 0) red[threadIdx.x >> 5] = lsum;
    __syncthreads();
    if (threadIdx.x < 8) {
        float t = red[threadIdx.x];
        #pragma unroll
        for (int o = 4; o; o >>= 1) t += __shfl_down_sync(0xffu, t, o);
        if (threadIdx.x == 0) red[0] = 1.f / (t + 1e-5f);
    }
    __syncthreads();
    float inv = red[0];
    #pragma unroll
    for (int it = 0; it < 4; it++) {
        int l = threadIdx.x + it*T;
        float vv = v[it] * inv;
        __nv_bfloat16 hb = __float2bfloat16(vv);
        g_ht_hi[(size_t)bp*L_ + l] = hb;
        g_ht_lo[(size_t)bp*L_ + l] = __float2bfloat16(vv - __bfloat162float(hb));
    }
}

// ---------------- generic mma GEMM core (128x128 tile, K-chunk 32) ---------
#define GA_PITCH 80
#define GB_PITCH 272
#define GSA_ 10240
#define GSB_ 8704
#define GSTAGE_ 37888
#define GSM_ 75776

__device__ __forceinline__ void g_load_stage(u32 sbase,
    const __nv_bfloat16* __restrict__ Ah, const __nv_bfloat16* __restrict__ Al,
    int lda,
    const __nv_bfloat16* __restrict__ Bh, const __nv_bfloat16* __restrict__ Bl,
    int ldb,
    int r0, int n0, int kc, int tid)
{
    #pragma unroll
    for (int t = 0; t < 2; t++) {
        int idx = tid + t*256;
        int row = idx >> 2, c = idx & 3;
        size_t so = (size_t)(r0+row)*lda + kc + c*8;
        cpa16(sbase + row*GA_PITCH + c*16, Ah + so);
        cpa16(sbase + GSA_ + row*GA_PITCH + c*16, Al + so);
    }
    #pragma unroll
    for (int t = 0; t < 2; t++) {
        int idx = tid + t*256;
        int row = idx >> 4, c = idx & 15;
        size_t so = (size_t)(kc+row)*ldb + n0 + c*8;
        cpa16(sbase + 2*GSA_ + row*GB_PITCH + c*16, Bh + so);
        cpa16(sbase + 2*GSA_ + GSB_ + row*GB_PITCH + c*16, Bl + so);
    }
}

__device__ __forceinline__ void g_compute(u32 sbase, int w, int l,
                                          float (*acc)[4]) {
    int wm = w >> 1, wn = w & 1;
    u32 abase = sbase + (u32)((wm*32 + (l&15))*GA_PITCH + (l>>4)*16);
    u32 bbase = sbase + 2*GSA_ +
                (u32)((l&15)*GB_PITCH + (wn*64 + (l>>4)*8)*2);
    #pragma unroll
    for (int kk = 0; kk < 2; kk++) {
        u32 ah[2][4], al[2][4];
        #pragma unroll
        for (int mi = 0; mi < 2; mi++) {
            ldsm4(abase + mi*16*GA_PITCH + kk*32,
                  ah[mi][0], ah[mi][1], ah[mi][2], ah[mi][3]);
            ldsm4(abase + GSA_ + mi*16*GA_PITCH + kk*32,
                  al[mi][0], al[mi][1], al[mi][2], al[mi][3]);
        }
        u32 bb = bbase + kk*16*GB_PITCH;
        #pragma unroll
        for (int ntp = 0; ntp < 4; ntp++) {
            u32 b0,b1,b2,b3, c0,c1,c2,c3;
            ldsm4t(bb + ntp*32, b0,b1,b2,b3);
            ldsm4t(bb + GSB_ + ntp*32, c0,c1,c2,c3);
            #pragma unroll
            for (int mi = 0; mi < 2; mi++) {
                float* A0 = acc[mi*8 + 2*ntp];
                float* A1 = acc[mi*8 + 2*ntp + 1];
                mma16816(A0, ah[mi][0],ah[mi][1],ah[mi][2],ah[mi][3], b0,b1);
                mma16816(A1, ah[mi][0],ah[mi][1],ah[mi][2],ah[mi][3], b2,b3);
                mma16816(A0, ah[mi][0],ah[mi][1],ah[mi][2],ah[mi][3], c0,c1);
                mma16816(A1, ah[mi][0],ah[mi][1],ah[mi][2],ah[mi][3], c2,c3);
                mma16816(A0, al[mi][0],al[mi][1],al[mi][2],al[mi][3], b0,b1);
                mma16816(A1, al[mi][0],al[mi][1],al[mi][2],al[mi][3], b2,b3);
            }
        }
    }
}

// full GEMM body with fp32 epilogue at out[row*ldo + col]
__device__ __forceinline__ void gemm_body(u32 sb, int tid, int w, int l,
    const __nv_bfloat16* Ah, const __nv_bfloat16* Al, int lda,
    const __nv_bfloat16* Bh, const __nv_bfloat16* Bl, int ldb,
    int r0, int n0, int kb, int NK, float* out, int ldo)
{
    float acc[16][4];
    #pragma unroll
    for (int f = 0; f < 16; f++)
        #pragma unroll
        for (int e = 0; e < 4; e++) acc[f][e] = 0.f;
    g_load_stage(sb, Ah, Al, lda, Bh, Bl, ldb, r0, n0, kb, tid);  cpa_commit();
    g_load_stage(sb+GSTAGE_, Ah, Al, lda, Bh, Bl, ldb, r0, n0, kb+32, tid); cpa_commit();
    for (int i = 0; i < NK; i++) {
        cpa_wait1(); __syncthreads();
        g_compute(sb + (i&1)*GSTAGE_, w, l, acc);
        __syncthreads();
        if (i + 2 < NK)
            g_load_stage(sb + (i&1)*GSTAGE_, Ah, Al, lda, Bh, Bl, ldb, r0, n0, kb+(i+2)*32, tid);
        cpa_commit();
    }
    int wm = w >> 1, wn = w & 1, g = l >> 2, tg = l & 3;
    #pragma unroll
    for (int mi = 0; mi < 2; mi++) {
        int row = r0 + wm*32 + mi*16 + g;
        #pragma unroll
        for (int f = 0; f < 8; f++) {
            int col = n0 + wn*64 + f*8 + tg*2;
            float* a4 = acc[mi*8 + f];
            out[(size_t)row*ldo + col]       = a4[0];
            out[(size_t)row*ldo + col+1]     = a4[1];
            out[(size_t)(row+8)*ldo + col]   = a4[2];
            out[(size_t)(row+8)*ldo + col+1] = a4[3];
        }
    }
}

// ---------------- kernel D: rs GEMM, K-split x2, 2 blocks/SM ---------------
__global__ void __launch_bounds__(256, 2) k_rs_mma() {
    extern __shared__ char smem[];
    u32 sb = smem_u32(smem);
    int tid = threadIdx.x, w = tid >> 5, l = tid & 31;
    int r0 = blockIdx.x * 128, n0 = blockIdx.y * 128;
    int khalf = blockIdx.z;
    int b = r0 / P_;
    gemm_body(sb, tid, w, l,
              g_ht_hi, g_ht_lo, L_,
              g_seq_hi + (size_t)b*L_*D_, g_seq_lo + (size_t)b*L_*D_, D_,
              r0, n0, khalf*(L_/2), (L_/2)/32,
              g_rsp + (size_t)khalf*BP_*D_, D_);
}

// ---------------- kernel D2: combine rs partials -> bf16 split -------------
__global__ void k_rs_comb() {
    int i2 = blockIdx.x*256 + threadIdx.x;
    if (i2 >= BP_*D_/2) return;
    float2 a = ((const float2*)g_rsp)[i2];
    float2 b = ((const float2*)(g_rsp + (size_t)BP_*D_))[i2];
    float v0 = a.x + b.x, v1 = a.y + b.y;
    u32 hp = cvt_bf2(v0, v1);
    u32 lp = cvt_bf2(v0 - bf_lo_f(hp), v1 - bf_hi_f(hp));
    ((u32*)g_rs_hi)[i2] = hp;
    ((u32*)g_rs_lo)[i2] = lp;
}

// ---------------- kernel E: merged E1 (384 blocks) + E0 (24 blocks) --------
#define NBE1_ (16*12*2)      // 384
__global__ void __launch_bounds__(256, 2) k_E01() {
    extern __shared__ char smem[];
    u32 sb = smem_u32(smem);
    int tid = threadIdx.x, w = tid >> 5, l = tid & 31;
    int bb = blockIdx.x;
    if (bb < NBE1_) {
        int khalf = bb & 1;
        int t = bb >> 1;
        int r0 = (t & 15) * 128, n0 = (t >> 4) * 128;
        gemm_body(sb, tid, w, l,
                  g_rs_hi, g_rs_lo, D_,
                  g_W2c_hi, g_W2c_lo, NW_,
                  r0, n0, khalf*(D_/2), (D_/2)/32,
                  g_ep + (size_t)khalf*BP_*NW_, NW_);
    } else {
        int t = bb - NBE1_;                  // 0..23
        int r0 = (t & 1) * 128, n0 = (t >> 1) * 128;
        gemm_body(sb, tid, w, l,
                  g_entA_hi, g_entA_lo, D_,
                  g_W1c_hi, g_W1c_lo, NW_,
                  r0, n0, 0, D_/32,
                  g_E0, NW_);
    }
}

// ---------------- kernel T: combine E0(gather) + E1 partials + tanh --------
__global__ void k_tanh(const int* __restrict__ hts,
                       const float* __restrict__ bh, const float* __restrict__ bt) {
    int i4 = blockIdx.x*blockDim.x + threadIdx.x;
    if (i4 >= BP_*NW_/4) return;
    int row = (i4*4) / NW_;
    int n   = (i4*4) % NW_;
    int sel = (n >= D_) ? 1 : 0;
    int col = n - sel*D_;
    int b = row / P_;
    int eidx = hts[row*2 + sel];
    int entrow = b*NE_ + eidx;
    const float4 a = ((const float4*)(g_ep))[i4];
    const float4 c = ((const float4*)(g_ep + (size_t)BP_*NW_))[i4];
    const float4 e0 = *(const float4*)(g_E0 + (size_t)entrow*NW_ + n);
    const float* bias = sel ? bt : bh;
    float4 bb = *(const float4*)(bias + col);
    float* out = sel ? g_zo : g_zs;
    float4 o;
    o.x = tanhf(a.x + c.x + e0.x + bb.x);
    o.y = tanhf(a.y + c.y + e0.y + bb.y);
    o.z = tanhf(a.z + c.z + e0.z + bb.z);
    o.w = tanhf(a.w + c.w + e0.w + bb.w);
    *(float4*)(out + (size_t)row*D_ + col) = o;
}

// ---------------- kernel F: bilinear classifier, fp16 single, 1 ldsm/2 MMA -
#define SM_ZSB 0                        // [128][24] f32 = 12288
#define SM_WB  12288
#define WSTAGE2_ 17408                  // one fp16 W tile per stage
#define SMEMB_ (SM_WB + 2*WSTAGE2_)     // 47104

__global__ void __launch_bounds__(256, 2) k_bilinear_mma() {
    extern __shared__ char smem[];
    float* zs_s = (float*)(smem + SM_ZSB);
    u32 sw = smem_u32(smem) + SM_WB;
    int tid = threadIdx.x, w = tid >> 5, l = tid & 31;
    int g = l >> 2, tg = l & 3;
    int k  = blockIdx.y;
    int r0 = blockIdx.x * 128;
    int iseg = blockIdx.z;
    int i0 = iseg*21, i1 = (iseg == ISEG_-1) ? BLK_ : (i0 + 21);
    int LEN = i1 - i0;

    // ---- prologue: W stages for i0, i0+1 ----
    #pragma unroll
    for (int p = 0; p < 2; p++) {
        int ii = i0 + p;
        const char* src = (const char*)(g_Wb + (size_t)(k*BLK_ + ii)*WTILE_);
        u32 dst = sw + (ii & 1)*WSTAGE2_;
        #pragma unroll
        for (int t = 0; t < 5; t++) {
            int idx = tid + t*256;
            if (idx < 1088) cpa16(dst + idx*16, src + idx*16);
        }
        cpa_commit();
    }

    int rg = w*16 + g;
    // ---- zo fragment values from global (one-time) ----
    float2 zoA[4][2], zoB[4][2];
    {
        const float* zor0 = g_zo + (size_t)(r0+rg)*D_ + k*BLK_;
        const float* zor1 = g_zo + (size_t)(r0+rg+8)*D_ + k*BLK_;
        #pragma unroll
        for (int jc = 0; jc < 4; jc++) {
            zoA[jc][0] = *(const float2*)(zor0 + jc*16 + tg*2);
            zoA[jc][1] = *(const float2*)(zor0 + jc*16 + tg*2 + 8);
            zoB[jc][0] = *(const float2*)(zor1 + jc*16 + tg*2);
            zoB[jc][1] = *(const float2*)(zor1 + jc*16 + tg*2 + 8);
        }
    }
    // ---- stage zs i-range slice [128][LEN] ----
    for (int idx = tid; idx < 128*LEN; idx += 256) {
        int r = idx / LEN, c = idx % LEN;
        zs_s[r*24 + c] = g_zs[(size_t)(r0+r)*D_ + k*BLK_ + i0 + c];
    }

    float acc[14][4];
    #pragma unroll
    for (int t = 0; t < 14; t++)
        #pragma unroll
        for (int e = 0; e < 4; e++) acc[t][e] = 0.f;

    u32 laneoff = (u32)((l & 15)*272 + (l >> 4)*16);

    for (int i = i0; i < i1; i++) {
        int s = i & 1;
        cpa_wait1();
        __syncthreads();
        float zs0 = zs_s[rg*24 + (i - i0)];
        float zs1 = zs_s[(rg+8)*24 + (i - i0)];
        u32 sbase = sw + s*WSTAGE2_;
        #pragma unroll
        for (int jc = 0; jc < 4; jc++) {
            // single-fp16 A fragments (no residual -> no unpack, low regs)
            u32 a0 = cvt_h2(zs0*zoA[jc][0].x, zs0*zoA[jc][0].y);
            u32 a1 = cvt_h2(zs1*zoB[jc][0].x, zs1*zoB[jc][0].y);
            u32 a2 = cvt_h2(zs0*zoA[jc][1].x, zs0*zoA[jc][1].y);
            u32 a3 = cvt_h2(zs1*zoB[jc][1].x, zs1*zoB[jc][1].y);
            u32 rowb = sbase + (u32)(jc*16*272) + laneoff;
            #pragma unroll
            for (int ntp = 0; ntp < 7; ntp++) {
                u32 b0, b1, b2, b3;
                ldsm4t(rowb + ntp*32, b0, b1, b2, b3);
                mma16816h(acc[2*ntp],   a0,a1,a2,a3, b0, b1);
                mma16816h(acc[2*ntp+1], a0,a1,a2,a3, b2, b3);
            }
        }
        __syncthreads();
        if (i + 2 < i1) {
            const char* src = (const char*)(g_Wb + (size_t)(k*BLK_ + i + 2)*WTILE_);
            u32 dst = sw + s*WSTAGE2_;
            #pragma unroll
            for (int t = 0; t < 5; t++) {
                int idx = tid + t*256;
                if (idx < 1088) cpa16(dst + idx*16, src + idx*16);
            }
        }
        cpa_commit();
    }

    int slab = iseg*KCH_ + k;
    float* base0 = g_part + ((size_t)slab*BP_ + r0 + rg)*NL_;
    float* base1 = g_part + ((size_t)slab*BP_ + r0 + rg + 8)*NL_;
    #pragma unroll
    for (int nt = 0; nt < 13; nt++) {
        int n0 = nt*8 + tg*2;
        if (n0 < NL_) { base0[n0] = acc[nt][0]; base1[n0] = acc[nt][2]; }
        if (n0 + 1 < NL_) { base0[n0+1] = acc[nt][1]; base1[n0+1] = acc[nt][3]; }
    }
}

// ---------------- kernel G: reduce split-K partials + bias -----------------
__global__ void k_reduce(const float* __restrict__ bbi, float* __restrict__ out) {
    int idx = blockIdx.x*256 + threadIdx.x;
    if (idx >= BP_*NL_) return;
    int n = idx % NL_;
    float s = bbi[n];
    #pragma unroll
    for (int k = 0; k < KSLAB_; k++)
        s += g_part[(size_t)k*BP_*NL_ + idx];
    out[idx] = s;
}

// ---------------- launch ---------------------------------------------------
extern "C" void kernel_launch(void* const* d_in, const int* in_sizes, int n_in,
                              void* d_out, int out_size) {
    const float* seq  = (const float*)d_in[0];
    const float* att  = (const float*)d_in[1];
    const int*   mpos = (const int*)d_in[2];
    const int*   hts  = (const int*)d_in[3];
    const float* Wh   = (const float*)d_in[4];
    const float* bh   = (const float*)d_in[5];
    const float* Wt   = (const float*)d_in[6];
    const float* bt   = (const float*)d_in[7];
    const float* Wbi  = (const float*)d_in[8];
    const float* bbi  = (const float*)d_in[9];
    float* out = (float*)d_out;

    static bool attr_set = false;
    if (!attr_set) {
        cudaFuncSetAttribute(k_bilinear_mma,
            cudaFuncAttributeMaxDynamicSharedMemorySize, SMEMB_);
        cudaFuncSetAttribute(k_rs_mma,
            cudaFuncAttributeMaxDynamicSharedMemorySize, GSM_);
        cudaFuncSetAttribute(k_E01,
            cudaFuncAttributeMaxDynamicSharedMemorySize, GSM_);
        attr_set = true;
    }

    k_prep<<<NB_PREP, 256>>>(seq, Wh, Wt, Wbi, att, mpos);
    k_ht<<<B_*P_, 256>>>(hts);
    k_rs_mma<<<dim3(BP_/128, D_/128, 2), 256, GSM_>>>();
    k_rs_comb<<<(BP_*D_/2 + 255)/256, 256>>>();
    k_E01<<<NBE1_ + 24, 256, GSM_>>>();
    k_tanh<<<(BP_*NW_/4 + 255)/256, 256>>>(hts, bh, bt);
    k_bilinear_mma<<<dim3(BP_/128, KCH_, ISEG_), 256, SMEMB_>>>();
    k_reduce<<<(BP_*NL_ + 255)/256, 256>>>(bbi, out);
}